// round 5
// baseline (speedup 1.0000x reference)
#include <cuda_runtime.h>

#define NN 100000
#define NE 1200000
#define DD 64
#define ADJ_STRIDE 64
#define OVF_CAP 8192
#define NTILES (NN / 16)   // 6250

typedef unsigned long long u64;

// Scratch (device globals — no allocation allowed)
__device__ float g_H [NN * DD];           // layer-1 gather source (feats * nout)
__device__ float g_H2[NN * DD];           // layer-2 gather source (relu(..)*nout)
__device__ int   g_degout[NN];
__device__ int   g_cnt[NN];               // true in-degree
__device__ float g_nout[NN];
__device__ float g_nin[NN];
__device__ int   g_adj[NN * ADJ_STRIDE];  // padded in-adjacency: src ids per dst
__device__ int   g_ovf[OVF_CAP];          // overflow edge ids (expected empty)
__device__ int   g_ovf_cnt;

// ---------------------------------------------------------------------------
__global__ void k_zero() {
    int i = blockIdx.x * blockDim.x + threadIdx.x;
    if (i < NN) { g_degout[i] = 0; g_cnt[i] = 0; }
    if (i == 0) g_ovf_cnt = 0;
}

__global__ void k_build(const int* __restrict__ src, const int* __restrict__ dst) {
    int e = blockIdx.x * blockDim.x + threadIdx.x;
    if (e >= NE) return;
    int s = src[e], d = dst[e];
    atomicAdd(&g_degout[s], 1);
    int slot = atomicAdd(&g_cnt[d], 1);
    if (slot < ADJ_STRIDE) {
        g_adj[d * ADJ_STRIDE + slot] = s;
    } else {
        int o = atomicAdd(&g_ovf_cnt, 1);
        if (o < OVF_CAP) g_ovf[o] = e;
    }
}

__global__ void k_norm() {
    int i = blockIdx.x * blockDim.x + threadIdx.x;
    if (i < NN) {
        g_nout[i] = rsqrtf(fmaxf((float)g_degout[i], 1.0f));
        g_nin[i]  = rsqrtf(fmaxf((float)g_cnt[i],    1.0f));
    }
}

// H = feats * norm_out[row]
__global__ void k_scale(const float4* __restrict__ feats) {
    int t = blockIdx.x * blockDim.x + threadIdx.x;
    if (t < NN * (DD / 4)) {
        int row = t >> 4;
        float s = g_nout[row];
        float4 v = feats[t];
        v.x *= s; v.y *= s; v.z *= s; v.w *= s;
        reinterpret_cast<float4*>(g_H)[t] = v;
    }
}

// packed f32x2 FMA: acc(2xf32) += a(2xf32) * w(2xf32)   (full-rate fp32 path)
__device__ __forceinline__ void fma2(u64& acc, u64 a, u64 w) {
    asm("fma.rn.f32x2 %0, %1, %2, %0;" : "+l"(acc) : "l"(a), "l"(w));
}
__device__ __forceinline__ float hsum2(u64 p) {
    return __uint_as_float((unsigned)(p & 0xffffffffull)) +
           __uint_as_float((unsigned)(p >> 32));
}

// Fused per-layer kernel: gather-aggregate 16 rows -> smem (scaled by nin),
// then 16x64 @ 64x64 GEMM with fused epilogue.
//   LAYER==1: out = g_H2, epi = relu(.)*nout   (device-resolved symbols!)
//   LAYER==2: out = out_param (harness d_out), epi = identity
template <int LAYER>
__global__ void __launch_bounds__(256)
k_fused(const float* __restrict__ W, const float* __restrict__ b,
        const int* __restrict__ src, const int* __restrict__ dst,
        float* __restrict__ out_param) {
    __shared__ __align__(16) float  Wt[64 * 68];   // Wt[c*68+k] = W[k*64+c]; 17-float4 stride => conflict-free
    __shared__ float bs[64];
    __shared__ __align__(16) float4 rows[16 * 16];

    const float4* H4 = reinterpret_cast<const float4*>(LAYER == 1 ? g_H : g_H2);
    float* out = (LAYER == 1) ? g_H2 : out_param;

    const int t = threadIdx.x;
    for (int i = t; i < 4096; i += 256)
        Wt[(i & 63) * 68 + (i >> 6)] = W[i];
    if (t < 64) bs[t] = b[t];
    // (first __syncthreads below covers Wt/bs visibility)

    const int j  = t & 15;          // float4 lane within row
    const int nl = t >> 4;          // node-local 0..15
    const int c  = t & 63;          // output column
    const int rg = t >> 6;          // row group 0..3
    const ulonglong2* wrow = reinterpret_cast<const ulonglong2*>(&Wt[c * 68]);

    for (int tile = blockIdx.x; tile < NTILES; tile += gridDim.x) {
        // ---- gather phase: AGG row = sum_{s in adj[n]} H[s], then * nin ----
        {
            int n = tile * 16 + nl;
            int cnt = g_cnt[n];
            int lim = cnt < ADJ_STRIDE ? cnt : ADJ_STRIDE;
            const int* lst = &g_adj[n * ADJ_STRIDE];
            float4 acc = make_float4(0.f, 0.f, 0.f, 0.f);
            int k = 0;
            for (; k + 4 <= lim; k += 4) {
                int s0 = __ldg(&lst[k + 0]);
                int s1 = __ldg(&lst[k + 1]);
                int s2 = __ldg(&lst[k + 2]);
                int s3 = __ldg(&lst[k + 3]);
                float4 v0 = H4[s0 * 16 + j];
                float4 v1 = H4[s1 * 16 + j];
                float4 v2 = H4[s2 * 16 + j];
                float4 v3 = H4[s3 * 16 + j];
                acc.x += v0.x + v1.x + v2.x + v3.x;
                acc.y += v0.y + v1.y + v2.y + v3.y;
                acc.z += v0.z + v1.z + v2.z + v3.z;
                acc.w += v0.w + v1.w + v2.w + v3.w;
            }
            for (; k < lim; k++) {
                int s = __ldg(&lst[k]);
                float4 v = H4[s * 16 + j];
                acc.x += v.x; acc.y += v.y; acc.z += v.z; acc.w += v.w;
            }
            if (cnt > ADJ_STRIDE) {           // overflow edges (expected none)
                int oc = g_ovf_cnt; if (oc > OVF_CAP) oc = OVF_CAP;
                for (int i = 0; i < oc; i++) {
                    int e = g_ovf[i];
                    if (dst[e] == n) {
                        float4 v = H4[src[e] * 16 + j];
                        acc.x += v.x; acc.y += v.y; acc.z += v.z; acc.w += v.w;
                    }
                }
            }
            float s = g_nin[n];
            acc.x *= s; acc.y *= s; acc.z *= s; acc.w *= s;
            rows[nl * 16 + j] = acc;
        }
        __syncthreads();

        // ---- GEMM phase: 4 rows x 1 col per thread, packed f32x2 FMAs ----
        u64 a0 = 0, a1 = 0, a2 = 0, a3 = 0;
        const ulonglong2* r0 = reinterpret_cast<const ulonglong2*>(&rows[(rg * 4 + 0) * 16]);
        const ulonglong2* r1 = reinterpret_cast<const ulonglong2*>(&rows[(rg * 4 + 1) * 16]);
        const ulonglong2* r2 = reinterpret_cast<const ulonglong2*>(&rows[(rg * 4 + 2) * 16]);
        const ulonglong2* r3 = reinterpret_cast<const ulonglong2*>(&rows[(rg * 4 + 3) * 16]);
        #pragma unroll
        for (int k4 = 0; k4 < 16; k4++) {
            ulonglong2 wp = wrow[k4];
            ulonglong2 ap;
            ap = r0[k4]; fma2(a0, ap.x, wp.x); fma2(a0, ap.y, wp.y);
            ap = r1[k4]; fma2(a1, ap.x, wp.x); fma2(a1, ap.y, wp.y);
            ap = r2[k4]; fma2(a2, ap.x, wp.x); fma2(a2, ap.y, wp.y);
            ap = r3[k4]; fma2(a3, ap.x, wp.x); fma2(a3, ap.y, wp.y);
        }

        u64 av[4] = {a0, a1, a2, a3};
        #pragma unroll
        for (int rr = 0; rr < 4; rr++) {
            int row = tile * 16 + rg * 4 + rr;
            float val = hsum2(av[rr]) + bs[c];
            if (LAYER == 1) val = fmaxf(val, 0.f) * g_nout[row];
            out[row * DD + c] = val;
        }
        __syncthreads();   // protect rows[] before next tile's gather
    }
}

// ---------------------------------------------------------------------------
extern "C" void kernel_launch(void* const* d_in, const int* in_sizes, int n_in,
                              void* d_out, int out_size) {
    // Size-based input dispatch (robust to metadata ordering).
    const float* feats = 0;
    const int*   edgeA = 0;
    const int*   edgeB = 0;
    const float* Wv[2] = {0, 0};
    const float* bv[2] = {0, 0};
    int wi = 0, bi = 0;
    for (int i = 0; i < n_in; i++) {
        int sz = in_sizes[i];
        if (sz == NN * DD) {
            feats = (const float*)d_in[i];
        } else if (sz == NE) {
            if (!edgeA) edgeA = (const int*)d_in[i];
            else        edgeB = (const int*)d_in[i];
        } else if (sz == DD * DD) {
            if (wi < 2) Wv[wi++] = (const float*)d_in[i];
        } else if (sz == DD) {
            if (bi < 2) bv[bi++] = (const float*)d_in[i];
        }
    }
    const int* src = edgeA;   // insertion order: src precedes dst (verified R4)
    const int* dst = edgeB;
    const float* W1 = Wv[0]; const float* b1 = bv[0];
    const float* W2 = Wv[1]; const float* b2 = bv[1];
    float* out = (float*)d_out;

    const int T = 256;
    const int g_nodes = (NN + T - 1) / T;
    const int g_edges = (NE + T - 1) / T;
    const int g_vec   = (NN * 16 + T - 1) / T;   // 6250
    const int g_fused = 148 * 8;                  // persistent, ~8 blocks/SM

    // Graph structure (shared by both layers)
    k_zero<<<g_nodes, T>>>();
    k_build<<<g_edges, T>>>(src, dst);
    k_norm<<<g_nodes, T>>>();

    // Layer 1: H2 = relu((gather(H)*nin)@W1 + b1) * nout
    k_scale<<<g_vec, T>>>((const float4*)feats);        // H = feats * nout
    k_fused<1><<<g_fused, T>>>(W1, b1, src, dst, 0);

    // Layer 2: out = (gather(H2)*nin)@W2 + b2
    k_fused<2><<<g_fused, T>>>(W2, b2, src, dst, out);
}

// round 6
// speedup vs baseline: 1.1424x; 1.1424x over previous
#include <cuda_runtime.h>
#include <cuda_fp16.h>

#define NN 100000
#define NE 1200000
#define DD 64
#define ADJ_STRIDE 64
#define OVF_CAP 8192
#define NTILES (NN / 16)   // 6250

typedef unsigned long long u64;

// Scratch (device globals — no allocation allowed)
__device__ __half g_Hh [NN * DD];         // layer-1 gather source (feats*nout), fp16
__device__ __half g_H2h[NN * DD];         // layer-2 gather source, fp16
__device__ int   g_degout[NN];
__device__ int   g_cnt[NN];               // true in-degree
__device__ float g_nout[NN];
__device__ float g_nin[NN];
__device__ int   g_adj[NN * ADJ_STRIDE];  // padded in-adjacency: src ids per dst
__device__ int   g_ovf[OVF_CAP];          // overflow edge ids (expected empty)
__device__ int   g_ovf_cnt;
__device__ int   g_t1, g_t2;              // dynamic tile counters (layer 1/2)

// ---------------------------------------------------------------------------
__global__ void k_zero() {
    int i = blockIdx.x * blockDim.x + threadIdx.x;
    if (i < NN) { g_degout[i] = 0; g_cnt[i] = 0; }
    if (i == 0) { g_ovf_cnt = 0; g_t1 = 0; g_t2 = 0; }
}

__global__ void k_build(const int* __restrict__ src, const int* __restrict__ dst) {
    int e = blockIdx.x * blockDim.x + threadIdx.x;
    if (e >= NE) return;
    int s = src[e], d = dst[e];
    atomicAdd(&g_degout[s], 1);
    int slot = atomicAdd(&g_cnt[d], 1);
    if (slot < ADJ_STRIDE) {
        g_adj[d * ADJ_STRIDE + slot] = s;
    } else {
        int o = atomicAdd(&g_ovf_cnt, 1);
        if (o < OVF_CAP) g_ovf[o] = e;
    }
}

__global__ void k_norm() {
    int i = blockIdx.x * blockDim.x + threadIdx.x;
    if (i < NN) {
        g_nout[i] = rsqrtf(fmaxf((float)g_degout[i], 1.0f));
        g_nin[i]  = rsqrtf(fmaxf((float)g_cnt[i],    1.0f));
    }
}

// Hh = half(feats * norm_out[row])
__global__ void k_scale(const float4* __restrict__ feats) {
    int t = blockIdx.x * blockDim.x + threadIdx.x;
    if (t < NN * (DD / 4)) {
        int row = t >> 4;
        float s = g_nout[row];
        float4 v = feats[t];
        __half2 h0 = __floats2half2_rn(v.x * s, v.y * s);
        __half2 h1 = __floats2half2_rn(v.z * s, v.w * s);
        uint2 u;
        u.x = *reinterpret_cast<unsigned*>(&h0);
        u.y = *reinterpret_cast<unsigned*>(&h1);
        reinterpret_cast<uint2*>(g_Hh)[t] = u;
    }
}

// packed f32x2 FMA (full-rate fp32 path on sm_103a)
__device__ __forceinline__ void fma2(u64& acc, u64 a, u64 w) {
    asm("fma.rn.f32x2 %0, %1, %2, %0;" : "+l"(acc) : "l"(a), "l"(w));
}
__device__ __forceinline__ float hsum2(u64 p) {
    return __uint_as_float((unsigned)(p & 0xffffffffull)) +
           __uint_as_float((unsigned)(p >> 32));
}
// acc.xyzw += 4 halves packed in uint2
__device__ __forceinline__ void acc4h(float4& a, uint2 u) {
    float2 f0 = __half22float2(*reinterpret_cast<__half2*>(&u.x));
    float2 f1 = __half22float2(*reinterpret_cast<__half2*>(&u.y));
    a.x += f0.x; a.y += f0.y; a.z += f1.x; a.w += f1.y;
}

// Fused per-layer kernel: gather-aggregate 16 rows -> smem (scaled by nin),
// then 16x64 @ 64x64 GEMM with fused epilogue. Dynamic tile scheduling.
//   LAYER==1: out = g_H2h (half), epi = relu(.)*nout
//   LAYER==2: out = out_param (fp32 d_out), epi = identity
template <int LAYER>
__global__ void __launch_bounds__(256, 6)
k_fused(const float* __restrict__ W, const float* __restrict__ b,
        const int* __restrict__ src, const int* __restrict__ dst,
        float* __restrict__ out_param) {
    __shared__ __align__(16) float  Wt[64 * 68];  // Wt[c*68+k]=W[k*64+c]; stride 17 f4 => conflict-free
    __shared__ float bs[64];
    __shared__ __align__(16) float4 rows[16 * 16];
    __shared__ int s_tile;

    const uint2* Hv = reinterpret_cast<const uint2*>(LAYER == 1 ? g_Hh : g_H2h);
    int* ctr = (LAYER == 1) ? &g_t1 : &g_t2;

    const int t = threadIdx.x;
    for (int i = t; i < 4096; i += 256)
        Wt[(i & 63) * 68 + (i >> 6)] = W[i];
    if (t < 64) bs[t] = b[t];

    const int j  = t & 15;          // 4-half chunk within row
    const int nl = t >> 4;          // node-local 0..15
    const int c  = t & 63;          // output column
    const int rg = t >> 6;          // row group 0..3
    const ulonglong2* wrow = reinterpret_cast<const ulonglong2*>(&Wt[c * 68]);

    for (;;) {
        if (t == 0) s_tile = atomicAdd(ctr, 1);
        __syncthreads();            // also covers Wt/bs on first iteration
        int tile = s_tile;
        if (tile >= NTILES) break;

        // ---- gather phase: row(n) = (sum_{s in adj[n]} H[s]) * nin[n] ----
        {
            int n = tile * 16 + nl;
            int cnt = g_cnt[n];
            int lim = cnt < ADJ_STRIDE ? cnt : ADJ_STRIDE;
            const int* lst = &g_adj[n * ADJ_STRIDE];
            float4 acc = make_float4(0.f, 0.f, 0.f, 0.f);
            int k = 0;
            for (; k + 4 <= lim; k += 4) {
                int4 s4 = *reinterpret_cast<const int4*>(&lst[k]);   // broadcast
                uint2 u0 = Hv[s4.x * 16 + j];
                uint2 u1 = Hv[s4.y * 16 + j];
                uint2 u2 = Hv[s4.z * 16 + j];
                uint2 u3 = Hv[s4.w * 16 + j];
                acc4h(acc, u0); acc4h(acc, u1); acc4h(acc, u2); acc4h(acc, u3);
            }
            for (; k < lim; k++) {
                uint2 u = Hv[__ldg(&lst[k]) * 16 + j];
                acc4h(acc, u);
            }
            if (cnt > ADJ_STRIDE) {             // overflow (expected none)
                int oc = g_ovf_cnt; if (oc > OVF_CAP) oc = OVF_CAP;
                for (int i = 0; i < oc; i++) {
                    int e = g_ovf[i];
                    if (dst[e] == n) acc4h(acc, Hv[src[e] * 16 + j]);
                }
            }
            float s = g_nin[n];
            acc.x *= s; acc.y *= s; acc.z *= s; acc.w *= s;
            rows[nl * 16 + j] = acc;
        }
        __syncthreads();

        // ---- GEMM phase: 4 rows x 1 col per thread, packed f32x2 FMAs ----
        u64 a0 = 0, a1 = 0, a2 = 0, a3 = 0;
        const ulonglong2* r0 = reinterpret_cast<const ulonglong2*>(&rows[(rg * 4 + 0) * 16]);
        const ulonglong2* r1 = reinterpret_cast<const ulonglong2*>(&rows[(rg * 4 + 1) * 16]);
        const ulonglong2* r2 = reinterpret_cast<const ulonglong2*>(&rows[(rg * 4 + 2) * 16]);
        const ulonglong2* r3 = reinterpret_cast<const ulonglong2*>(&rows[(rg * 4 + 3) * 16]);
        #pragma unroll
        for (int k4 = 0; k4 < 16; k4++) {
            ulonglong2 wp = wrow[k4];
            ulonglong2 ap;
            ap = r0[k4]; fma2(a0, ap.x, wp.x); fma2(a0, ap.y, wp.y);
            ap = r1[k4]; fma2(a1, ap.x, wp.x); fma2(a1, ap.y, wp.y);
            ap = r2[k4]; fma2(a2, ap.x, wp.x); fma2(a2, ap.y, wp.y);
            ap = r3[k4]; fma2(a3, ap.x, wp.x); fma2(a3, ap.y, wp.y);
        }

        u64 av[4] = {a0, a1, a2, a3};
        #pragma unroll
        for (int rr = 0; rr < 4; rr++) {
            int row = tile * 16 + rg * 4 + rr;
            float val = hsum2(av[rr]) + bs[c];
            if (LAYER == 1) {
                val = fmaxf(val, 0.f) * g_nout[row];
                g_H2h[row * DD + c] = __float2half_rn(val);
            } else {
                out_param[row * DD + c] = val;
            }
        }
        __syncthreads();   // protect rows[] before next tile's gather
    }
}

// ---------------------------------------------------------------------------
extern "C" void kernel_launch(void* const* d_in, const int* in_sizes, int n_in,
                              void* d_out, int out_size) {
    // Size-based input dispatch (robust to metadata ordering).
    const float* feats = 0;
    const int*   edgeA = 0;
    const int*   edgeB = 0;
    const float* Wv[2] = {0, 0};
    const float* bv[2] = {0, 0};
    int wi = 0, bi = 0;
    for (int i = 0; i < n_in; i++) {
        int sz = in_sizes[i];
        if (sz == NN * DD) {
            feats = (const float*)d_in[i];
        } else if (sz == NE) {
            if (!edgeA) edgeA = (const int*)d_in[i];
            else        edgeB = (const int*)d_in[i];
        } else if (sz == DD * DD) {
            if (wi < 2) Wv[wi++] = (const float*)d_in[i];
        } else if (sz == DD) {
            if (bi < 2) bv[bi++] = (const float*)d_in[i];
        }
    }
    const int* src = edgeA;   // insertion order: src precedes dst (verified R4)
    const int* dst = edgeB;
    const float* W1 = Wv[0]; const float* b1 = bv[0];
    const float* W2 = Wv[1]; const float* b2 = bv[1];
    float* out = (float*)d_out;

    const int T = 256;
    const int g_nodes = (NN + T - 1) / T;
    const int g_edges = (NE + T - 1) / T;
    const int g_vec   = (NN * 16 + T - 1) / T;   // 6250
    const int g_fused = 148 * 6;                  // matches __launch_bounds__(256,6)

    // Graph structure (shared by both layers)
    k_zero<<<g_nodes, T>>>();
    k_build<<<g_edges, T>>>(src, dst);
    k_norm<<<g_nodes, T>>>();

    // Layer 1: H2 = half(relu((gather(H)*nin)@W1 + b1) * nout)
    k_scale<<<g_vec, T>>>((const float4*)feats);
    k_fused<1><<<g_fused, T>>>(W1, b1, src, dst, 0);

    // Layer 2: out = (gather(H2)*nin)@W2 + b2
    k_fused<2><<<g_fused, T>>>(W2, b2, src, dst, out);
}

// round 8
// speedup vs baseline: 1.6699x; 1.4617x over previous
#include <cuda_runtime.h>
#include <cuda_fp16.h>

#define NN 100000
#define NE 1200000
#define DD 64
#define ADJ_STRIDE 64
#define OVF_CAP 8192
#define NTM 782                 // ceil(100000/128) GEMM tiles
#define SW128(o) ((o) ^ ((((o) >> 3)) & 0x70))

typedef unsigned long long u64;

// Scratch (device globals — no allocation allowed)
__device__ __half g_Hh  [NN * DD];        // layer-1 gather source (feats*nout)
__device__ __half g_H2h [NN * DD];        // layer-2 gather source
__device__ __half g_AGGh[NN * DD];        // gather output = GEMM A operand
__device__ int   g_degout[NN];
__device__ int   g_cnt[NN];
__device__ float g_nout[NN];
__device__ float g_nin[NN];
__device__ int   g_adj[NN * ADJ_STRIDE];
__device__ int   g_ovf[OVF_CAP];
__device__ int   g_ovf_cnt;

// ---------------------------------------------------------------------------
__global__ void k_zero() {
    int i = blockIdx.x * blockDim.x + threadIdx.x;
    if (i < NN) { g_degout[i] = 0; g_cnt[i] = 0; }
    if (i == 0) g_ovf_cnt = 0;
}

__global__ void k_build(const int* __restrict__ src, const int* __restrict__ dst) {
    int e = blockIdx.x * blockDim.x + threadIdx.x;
    if (e >= NE) return;
    int s = src[e], d = dst[e];
    atomicAdd(&g_degout[s], 1);
    int slot = atomicAdd(&g_cnt[d], 1);
    if (slot < ADJ_STRIDE) g_adj[d * ADJ_STRIDE + slot] = s;
    else { int o = atomicAdd(&g_ovf_cnt, 1); if (o < OVF_CAP) g_ovf[o] = e; }
}

__global__ void k_norm() {
    int i = blockIdx.x * blockDim.x + threadIdx.x;
    if (i < NN) {
        g_nout[i] = rsqrtf(fmaxf((float)g_degout[i], 1.0f));
        g_nin[i]  = rsqrtf(fmaxf((float)g_cnt[i],    1.0f));
    }
}

__global__ void k_scale(const float4* __restrict__ feats) {
    int t = blockIdx.x * blockDim.x + threadIdx.x;
    if (t < NN * 16) {
        float s = g_nout[t >> 4];
        float4 v = feats[t];
        __half2 h0 = __floats2half2_rn(v.x * s, v.y * s);
        __half2 h1 = __floats2half2_rn(v.z * s, v.w * s);
        uint2 u;
        u.x = *reinterpret_cast<unsigned*>(&h0);
        u.y = *reinterpret_cast<unsigned*>(&h1);
        reinterpret_cast<uint2*>(g_Hh)[t] = u;
    }
}

__device__ __forceinline__ void acc4h(float4& a, uint2 u) {
    float2 f0 = __half22float2(*reinterpret_cast<__half2*>(&u.x));
    float2 f1 = __half22float2(*reinterpret_cast<__half2*>(&u.y));
    a.x += f0.x; a.y += f0.y; a.z += f1.x; a.w += f1.y;
}

// Gather: AGGh[n] = half( (sum_{s in adj[n]} H[s]) * nin[n] )
template <int LAYER>
__global__ void __launch_bounds__(256) k_agg(const int* __restrict__ src,
                                             const int* __restrict__ dst) {
    int t = blockIdx.x * blockDim.x + threadIdx.x;
    if (t >= NN * 16) return;
    int n = t >> 4, j = t & 15;
    const uint2* Hv = reinterpret_cast<const uint2*>(LAYER == 1 ? g_Hh : g_H2h);
    int cnt = g_cnt[n];
    int lim = cnt < ADJ_STRIDE ? cnt : ADJ_STRIDE;
    const int* lst = &g_adj[n * ADJ_STRIDE];
    float4 acc = make_float4(0.f, 0.f, 0.f, 0.f);
    int k = 0;
    for (; k + 4 <= lim; k += 4) {
        int4 s4 = *reinterpret_cast<const int4*>(&lst[k]);
        uint2 u0 = Hv[s4.x * 16 + j];
        uint2 u1 = Hv[s4.y * 16 + j];
        uint2 u2 = Hv[s4.z * 16 + j];
        uint2 u3 = Hv[s4.w * 16 + j];
        acc4h(acc, u0); acc4h(acc, u1); acc4h(acc, u2); acc4h(acc, u3);
    }
    for (; k < lim; k++) acc4h(acc, Hv[__ldg(&lst[k]) * 16 + j]);
    if (cnt > ADJ_STRIDE) {
        int oc = g_ovf_cnt; if (oc > OVF_CAP) oc = OVF_CAP;
        for (int i = 0; i < oc; i++) {
            int e = g_ovf[i];
            if (dst[e] == n) acc4h(acc, Hv[src[e] * 16 + j]);
        }
    }
    float s = g_nin[n];
    __half2 h0 = __floats2half2_rn(acc.x * s, acc.y * s);
    __half2 h1 = __floats2half2_rn(acc.z * s, acc.w * s);
    uint2 u;
    u.x = *reinterpret_cast<unsigned*>(&h0);
    u.y = *reinterpret_cast<unsigned*>(&h1);
    reinterpret_cast<uint2*>(g_AGGh)[t] = u;
}

// ---------------------------------------------------------------------------
// Warp-MMA GEMM (HMMA, no arch-suffixed PTX): D(128x64) = A(128x64) @ W(64x64)
// A fp16 swizzled smem; B = W^T stored [n][k] row-major fp16 swizzled.
__device__ __forceinline__ unsigned smem_u32(const void* p) {
    unsigned a;
    asm("{ .reg .u64 t; cvta.to.shared.u64 t, %1; cvt.u32.u64 %0, t; }" : "=r"(a) : "l"(p));
    return a;
}
__device__ __forceinline__ void ldmx4(unsigned& r0, unsigned& r1, unsigned& r2,
                                      unsigned& r3, unsigned addr) {
    asm volatile("ldmatrix.sync.aligned.m8n8.x4.shared.b16 {%0,%1,%2,%3}, [%4];"
                 : "=r"(r0), "=r"(r1), "=r"(r2), "=r"(r3) : "r"(addr));
}
__device__ __forceinline__ void mma16816(float* d, unsigned a0, unsigned a1,
                                         unsigned a2, unsigned a3,
                                         unsigned b0, unsigned b1) {
    asm volatile(
        "mma.sync.aligned.m16n8k16.row.col.f32.f16.f16.f32 "
        "{%0,%1,%2,%3}, {%4,%5,%6,%7}, {%8,%9}, {%0,%1,%2,%3};"
        : "+f"(d[0]), "+f"(d[1]), "+f"(d[2]), "+f"(d[3])
        : "r"(a0), "r"(a1), "r"(a2), "r"(a3), "r"(b0), "r"(b1));
}

template <int LAYER>
__global__ void __launch_bounds__(128)
k_gemm_mma(const float* __restrict__ W, const float* __restrict__ bias,
           float* __restrict__ out_param) {
    __shared__ __align__(16) __half sA[128 * 64];   // 16KB, SW128-swizzled rows
    __shared__ __align__(16) __half sB[64 * 64];    // 8KB,  [n][k] swizzled
    __shared__ float bs[64];

    const int t = threadIdx.x;
    const int wid = t >> 5, lane = t & 31;

    // B[n][k] = W[k][n]
    for (int i = t; i < 4096; i += 128) {
        int k = i >> 6, c = i & 63;
        *reinterpret_cast<__half*>(
            reinterpret_cast<char*>(sB) + SW128(c * 128 + k * 2)) = __float2half_rn(W[i]);
    }
    if (t < 64) bs[t] = bias[t];

    // A: row t of this 128-row tile
    int gr = blockIdx.x * 128 + t;
    {
        const uint4* a4 = reinterpret_cast<const uint4*>(g_AGGh);
        #pragma unroll
        for (int ch = 0; ch < 8; ch++) {
            uint4 v = make_uint4(0u, 0u, 0u, 0u);
            if (gr < NN) v = a4[gr * 8 + ch];
            *reinterpret_cast<uint4*>(
                reinterpret_cast<char*>(sA) + SW128(t * 128 + ch * 16)) = v;
        }
    }
    __syncthreads();

    const unsigned baseA = smem_u32(sA);
    const unsigned baseB = smem_u32(sB);
    const int lrow = lane & 15;             // ldmatrix row within 16-tile
    const int lcol = (lane >> 4) * 16;      // ldmatrix byte-col within 32B k-chunk

    float d[2][8][4];
    #pragma unroll
    for (int i = 0; i < 2; i++)
        #pragma unroll
        for (int j = 0; j < 8; j++)
            #pragma unroll
            for (int q = 0; q < 4; q++) d[i][j][q] = 0.f;

    #pragma unroll
    for (int kk = 0; kk < 4; kk++) {        // k-steps of 16
        unsigned a[2][4];
        #pragma unroll
        for (int i = 0; i < 2; i++) {
            int row = wid * 32 + i * 16 + lrow;
            unsigned addr = baseA + SW128(row * 128 + kk * 32 + lcol);
            ldmx4(a[i][0], a[i][1], a[i][2], a[i][3], addr);
        }
        #pragma unroll
        for (int p = 0; p < 4; p++) {       // n-pairs (16 cols each)
            unsigned r0, r1, r2, r3;
            int nrow = p * 16 + lrow;
            unsigned addr = baseB + SW128(nrow * 128 + kk * 32 + lcol);
            ldmx4(r0, r1, r2, r3, addr);
            #pragma unroll
            for (int i = 0; i < 2; i++) {
                mma16816(d[i][p * 2 + 0], a[i][0], a[i][1], a[i][2], a[i][3], r0, r2);
                mma16816(d[i][p * 2 + 1], a[i][0], a[i][1], a[i][2], a[i][3], r1, r3);
            }
        }
    }

    // Epilogue: thread holds (r0,c),(r0,c+1),(r1,c),(r1,c+1) per (i,j)
    const int g   = lane >> 2;
    const int tid = lane & 3;
    #pragma unroll
    for (int i = 0; i < 2; i++) {
        #pragma unroll
        for (int half = 0; half < 2; half++) {
            int row = blockIdx.x * 128 + wid * 32 + i * 16 + g + half * 8;
            if (row >= NN) continue;
            float no = (LAYER == 1) ? g_nout[row] : 0.f;
            #pragma unroll
            for (int j = 0; j < 8; j++) {
                int c = j * 8 + tid * 2;
                float v0 = d[i][j][half * 2 + 0] + bs[c];
                float v1 = d[i][j][half * 2 + 1] + bs[c + 1];
                if (LAYER == 1) {
                    v0 = fmaxf(v0, 0.f) * no;
                    v1 = fmaxf(v1, 0.f) * no;
                    __half2 h = __floats2half2_rn(v0, v1);
                    *reinterpret_cast<__half2*>(&g_H2h[row * DD + c]) = h;
                } else {
                    *reinterpret_cast<float2*>(&out_param[row * DD + c]) =
                        make_float2(v0, v1);
                }
            }
        }
    }
}

// ---------------------------------------------------------------------------
extern "C" void kernel_launch(void* const* d_in, const int* in_sizes, int n_in,
                              void* d_out, int out_size) {
    const float* feats = 0;
    const int *edgeA = 0, *edgeB = 0;
    const float* Wv[2] = {0, 0};
    const float* bv[2] = {0, 0};
    int wi = 0, bi = 0;
    for (int i = 0; i < n_in; i++) {
        int sz = in_sizes[i];
        if (sz == NN * DD)      feats = (const float*)d_in[i];
        else if (sz == NE)      { if (!edgeA) edgeA = (const int*)d_in[i]; else edgeB = (const int*)d_in[i]; }
        else if (sz == DD * DD) { if (wi < 2) Wv[wi++] = (const float*)d_in[i]; }
        else if (sz == DD)      { if (bi < 2) bv[bi++] = (const float*)d_in[i]; }
    }
    const int* src = edgeA;   // insertion order: src precedes dst (verified R4)
    const int* dst = edgeB;
    float* out = (float*)d_out;

    const int T = 256;
    const int g_nodes = (NN + T - 1) / T;
    const int g_edges = (NE + T - 1) / T;
    const int g_vec   = (NN * 16 + T - 1) / T;   // 6250

    k_zero <<<g_nodes, T>>>();
    k_build<<<g_edges, T>>>(src, dst);
    k_norm <<<g_nodes, T>>>();
    k_scale<<<g_vec,   T>>>((const float4*)feats);

    k_agg<1>     <<<g_vec, T>>>(src, dst);
    k_gemm_mma<1><<<NTM, 128>>>(Wv[0], bv[0], 0);

    k_agg<2>     <<<g_vec, T>>>(src, dst);
    k_gemm_mma<2><<<NTM, 128>>>(Wv[1], bv[1], out);
}